// round 16
// baseline (speedup 1.0000x reference)
#include <cuda_runtime.h>
#include <cuda_fp16.h>
#include <stdint.h>

// Problem constants
#define Bsz 8
#define Ssz 20
#define Fsz 200
#define Dsz 2048
#define Tn  20
#define En  128
#define Hn  128
#define CDn 300
#define THn 128
#define Mrows (Bsz*Ssz*Fsz)     // 32000
#define ROWS_PER_B (Ssz*Fsz)    // 4000

// Scratch (no allocations allowed)
__device__ float g_pool[Bsz*Dsz];
__device__ float g_venc[Bsz*Hn];
__device__ float g_vw3[Bsz*Hn];
__device__ float g_probs[Bsz*Tn];
__device__ float g_contrib[Tn*Hn];
__device__ int   g_cnt[Bsz];
__device__ __half g_Wh[Hn*Dsz];                   // W1^T fp16  [n][k]

// ---------------------------------------------------------------------------
__device__ __forceinline__ uint32_t smem_u32(const void* p) {
    uint32_t a;
    asm("{ .reg .u64 t; cvta.to.shared.u64 t, %1; cvt.u32.u64 %0, t; }"
        : "=r"(a) : "l"(p));
    return a;
}
__device__ __forceinline__ void mma16816h(float* d, const uint32_t* a, const uint32_t* b) {
    asm volatile(
        "mma.sync.aligned.m16n8k16.row.col.f32.f16.f16.f32 "
        "{%0,%1,%2,%3}, {%4,%5,%6,%7}, {%8,%9}, {%0,%1,%2,%3};"
        : "+f"(d[0]), "+f"(d[1]), "+f"(d[2]), "+f"(d[3])
        : "r"(a[0]), "r"(a[1]), "r"(a[2]), "r"(a[3]), "r"(b[0]), "r"(b[1]));
}
#define LDSM4(r0, r1, r2, r3, addr) \
    asm volatile("ldmatrix.sync.aligned.m8n8.x4.shared.b16 {%0,%1,%2,%3}, [%4];" \
                 : "=r"(r0), "=r"(r1), "=r"(r2), "=r"(r3) : "r"(addr))
#define CP_ASYNC16(dst, src) \
    asm volatile("cp.async.cg.shared.global [%0], [%1], 16;" :: "r"(dst), "l"(src))
#define CP_COMMIT() asm volatile("cp.async.commit_group;")
#define CP_WAIT4()  asm volatile("cp.async.wait_group 4;")
#define CP_WAIT3()  asm volatile("cp.async.wait_group 3;")
#define CP_WAIT2()  asm volatile("cp.async.wait_group 2;")
#define CP_WAIT0()  asm volatile("cp.async.wait_group 0;")

__device__ __forceinline__ uint32_t packh2(__half a, __half b) {
    __half2 h = __halves2half2(a, b);
    return *(uint32_t*)&h;
}

// ---------------------------------------------------------------------------
// prep: contrib (0..19) + zero g_pool (20..83) + W1 transpose (84..115)
// + zero g_venc/g_cnt (116).  grid 117 x 256
// ---------------------------------------------------------------------------
__global__ void prep_kernel(const float* __restrict__ W1,
                            const float* __restrict__ topic_emb,
                            const float* __restrict__ W2) {
    int bx = blockIdx.x, tid = threadIdx.x;
    if (bx < Tn) {
        __shared__ float red[2][Hn];
        int h = tid & 127, e2 = tid >> 7;
        float acc = 0.f;
        int e0 = e2 * 64;
        #pragma unroll 8
        for (int e = e0; e < e0 + 64; e++)
            acc += topic_emb[bx * En + e] * W2[e * Hn + h];
        red[e2][h] = acc;
        __syncthreads();
        if (e2 == 0) g_contrib[bx * Hn + h] = red[0][h] + red[1][h];
    } else if (bx < Tn + 64) {
        g_pool[(bx - Tn) * 256 + tid] = 0.f;
    } else if (bx < Tn + 96) {
        __shared__ __half tile[64][132];
        int k0 = (bx - Tn - 64) * 64;
        #pragma unroll
        for (int p = 0; p < 8; p++) {
            int fidx = p * 256 + tid;
            int row = fidx >> 5, c4 = (fidx & 31) * 4;
            float4 v = *(const float4*)(W1 + (size_t)(k0 + row) * Hn + c4);
            tile[row][c4]     = __float2half_rn(v.x);
            tile[row][c4 + 1] = __float2half_rn(v.y);
            tile[row][c4 + 2] = __float2half_rn(v.z);
            tile[row][c4 + 3] = __float2half_rn(v.w);
        }
        __syncthreads();
        int n = tid >> 1, kh = (tid & 1) * 32;
        __half* dst = g_Wh + (size_t)n * Dsz + k0 + kh;
        uint32_t w[16];
        #pragma unroll
        for (int j = 0; j < 16; j++)
            w[j] = packh2(tile[kh + 2 * j][n], tile[kh + 2 * j + 1][n]);
        #pragma unroll
        for (int j = 0; j < 4; j++)
            *(uint4*)(dst + 8 * j) = make_uint4(w[4 * j], w[4 * j + 1],
                                                w[4 * j + 2], w[4 * j + 3]);
    } else {
        #pragma unroll
        for (int j = 0; j < 4; j++)
            g_venc[j * 256 + tid] = 0.f;
        if (tid < Bsz) g_cnt[tid] = 0;
    }
}

// grid (8, 20, 32): z = b*4 + f-quarter, 256 threads (fp32 batch)
__global__ void pool_kernel(const float* __restrict__ batch,
                            const int* __restrict__ seg_len) {
    int b = blockIdx.z >> 2, fq = blockIdx.z & 3, s = blockIdx.y;
    int d = blockIdx.x * 256 + threadIdx.x;
    int len = seg_len[b * Ssz + s];
    int f0 = fq * 50;
    int f1 = min(len, f0 + 50);
    if (f0 >= f1) return;
    const float* p = batch + ((size_t)(b * Ssz + s)) * Fsz * Dsz + d;
    float acc = 0.f;
    #pragma unroll 5
    for (int f = f0; f < f1; f++) acc += p[(size_t)f * Dsz];
    atomicAdd(&g_pool[b * Dsz + d], acc);
}

// ---------------------------------------------------------------------------
// encsmall: grid (Bsz, 5) x 1024.
// ---------------------------------------------------------------------------
__global__ void encsmall_kernel(const int* __restrict__ seg_len,
                                const float* __restrict__ concept1,
                                const float* __restrict__ concept2,
                                const float* __restrict__ W_enc,
                                const float* __restrict__ Wc1,
                                const float* __restrict__ Wc2,
                                const float* __restrict__ b_enc,
                                const float* __restrict__ Wt1,
                                const float* __restrict__ bt1,
                                const float* __restrict__ Wt2,
                                const float* __restrict__ bt2,
                                const float* __restrict__ W3) {
    int b = blockIdx.x, y = blockIdx.y;
    int tid = threadIdx.x;
    int h  = tid & 127;
    int sl = tid >> 7;                 // 0..7

    if (y < 4) {
        int cnt = 0;
        #pragma unroll
        for (int s = 0; s < Ssz; s++) cnt += seg_len[b * Ssz + s];
        float inv = 1.f / fmaxf((float)cnt, 1.f);
        int d0 = (y * 8 + sl) * 64;
        float acc = 0.f;
        #pragma unroll 8
        for (int i = 0; i < 64; i++)
            acc += g_pool[b * Dsz + d0 + i] * W_enc[(size_t)(d0 + i) * Hn + h];
        atomicAdd(&g_venc[b * Hn + h], acc * inv);
        __threadfence();
        __syncthreads();
        if (tid == 0) atomicAdd(&g_cnt[b], 1);
        return;
    }

    __shared__ float part[8][Hn];
    __shared__ float part2[8][Hn];
    __shared__ float video[Hn];
    __shared__ float th[THn];
    __shared__ float logits[Tn];

    {
        int c0 = sl * 38;
        int c1 = min(c0 + 38, CDn);
        float acc = 0.f;
        #pragma unroll 4
        for (int c = c0; c < c1; c++)
            acc += concept1[b * CDn + c] * Wc1[c * Hn + h]
                 + concept2[b * CDn + c] * Wc2[c * Hn + h];
        atomicAdd(&g_venc[b * Hn + h], acc);
    }

    int k0 = sl * 16;
    float wt1r[16], w3r[16];
    #pragma unroll
    for (int i = 0; i < 16; i++) {
        wt1r[i] = Wt1[(k0 + i) * THn + h];
        w3r[i]  = W3[(k0 + i) * Hn + h];
    }

    if (tid == 0) {
        while (atomicAdd(&g_cnt[b], 0) < 4) { }
    }
    __syncthreads();

    if (sl == 0) video[h] = fmaxf(g_venc[b * Hn + h] + b_enc[h], 0.f);
    __syncthreads();
    {
        float a2 = 0.f, a3 = 0.f;
        #pragma unroll
        for (int i = 0; i < 16; i++) {
            float v = video[k0 + i];
            a2 += v * wt1r[i];
            a3 += v * w3r[i];
        }
        part[sl][h] = a2;
        part2[sl][h] = a3;
    }
    __syncthreads();
    if (sl == 0) {
        float a2 = bt1[h], a3 = 0.f;
        #pragma unroll
        for (int j = 0; j < 8; j++) { a2 += part[j][h]; a3 += part2[j][h]; }
        th[h] = fmaxf(a2, 0.f);
        g_vw3[b * Hn + h] = a3;
    }
    __syncthreads();
    if (tid < Tn) {
        float a4 = bt2[tid];
        #pragma unroll 8
        for (int k = 0; k < THn; k++) a4 += th[k] * Wt2[k * Tn + tid];
        logits[tid] = a4;
    }
    __syncthreads();
    if (tid == 0) {
        float m = -1e30f;
        for (int t = 0; t < Tn; t++) m = fmaxf(m, logits[t]);
        float ssum = 0.f;
        for (int t = 0; t < Tn; t++) { float e = __expf(logits[t] - m); logits[t] = e; ssum += e; }
        float invs = 1.f / ssum;
        for (int t = 0; t < Tn; t++) g_probs[b * Tn + t] = logits[t] * invs;
    }
}

// ---------------------------------------------------------------------------
// single-fp16 GEMM (batch @ W1) + fused topic epilogue.
// BM=64, 256 threads, 8 warps (32x32 warp tiles), 2 CTAs per SM.
// A: cp.async fp32 3-stage ring -> LDS -> cvt -> STS fp16 double buffer.
// B: cp.async fp16 3-stage ring. Two barriers per chunk (issue A after bar1,
// issue B after bar2); co-resident CTA hides barrier stalls.
// ---------------------------------------------------------------------------
#define KCH   64
#define NCHK  (Dsz / KCH)               // 32
#define A16STG 8192                     // fp16 A stages at 0, 8192
#define OFF_A32 16384                   // fp32 A ring: 3 x 16384
#define A32STG  16384
#define OFF_B   65536                   // B ring: 3 x 16384
#define BSTG    16384
// epilogue constants overlay the A32 ring (dead after mainloop)
#define SM_CONTRIB 16384                // 10240 B
#define SM_VW3     26624                // 4096 B
#define SM_B1      30720                // 512 B
#define SM_WOUT    31232                // 512 B
#define SM_PROBS   31744                // 768 B
#define SM_RED     32768                // 4096 B  [64][4][4]
#define SM_BYTES   (114688 + 128)

__global__ __launch_bounds__(256, 2)
void gemm_tc_kernel(const float* __restrict__ batch,
                    const float* __restrict__ b1,
                    const float* __restrict__ w_out,
                    const float* __restrict__ b_out_p,
                    float* __restrict__ out,
                    int out_size) {
    extern __shared__ char smem_raw[];
    uint32_t sb0 = smem_u32(smem_raw);
    uint32_t sb = (sb0 + 127) & ~127u;
    char* smem = smem_raw + (sb - sb0);

    int tid = threadIdx.x;
    int wid = tid >> 5, lane = tid & 31;
    int m0 = blockIdx.x * 64;

    // ---- A32 cp.async mapping: 4 parts of 16B per thread (16KB stage) ----
    // part j: row = j*16 + (tid>>4), float col = (tid&15)*4
    uint32_t a32_off[4];
    const float* a32_src[4];
    int arow_c = tid >> 4;       // 0..15
    int acol_f = (tid & 15) * 4; // 0..60
    #pragma unroll
    for (int j = 0; j < 4; j++) {
        a32_off[j] = (uint32_t)(j * 4096 + tid * 16);
        a32_src[j] = batch + (size_t)(m0 + j * 16 + arow_c) * Dsz + acol_f;
    }
    uint32_t a16_sts[4];
    #pragma unroll
    for (int j = 0; j < 4; j++) {
        uint32_t r = (uint32_t)(j * 16 + arow_c);
        uint32_t cb = (uint32_t)((tid & 15) * 8);
        a16_sts[j] = r * 128 + (cb ^ ((r & 7) << 4));
    }

    // B cp.async: 4 x 16B per thread per chunk (16KB stage)
    int brow_g[4], bc16[4];
    uint32_t b_dst[4];
    #pragma unroll
    for (int j = 0; j < 4; j++) {
        int gid = tid + j * 256;
        brow_g[j] = gid >> 3;
        bc16[j] = gid & 7;
        b_dst[j] = (uint32_t)brow_g[j] * 128 +
                   (((uint32_t)(bc16[j] * 16)) ^ (((uint32_t)brow_g[j] & 7) << 4));
    }

    // ---- per-warp fragment mapping: 8 warps, warp tile 32x32 ----
    int wm = wid >> 2, wn = wid & 3;   // wm 0..1, wn 0..3
    int lr = lane & 7, s1 = (lane >> 3) & 1, s2 = lane >> 4;
    uint32_t a_base[2], a_xor[2];
    #pragma unroll
    for (int mt = 0; mt < 2; mt++) {
        int arow = wm * 32 + mt * 16 + s1 * 8 + lr;
        a_base[mt] = (uint32_t)arow * 128;
        a_xor[mt] = ((uint32_t)arow & 7) << 4;
    }
    uint32_t b_base[2], b_xor[2];
    #pragma unroll
    for (int np = 0; np < 2; np++) {
        int brow = wn * 32 + np * 16 + s2 * 8 + lr;
        b_base[np] = (uint32_t)brow * 128;
        b_xor[np] = ((uint32_t)brow & 7) << 4;
    }
    uint32_t a_kadd = (uint32_t)(s2 * 16);
    uint32_t b_kadd = (uint32_t)(s1 * 16);

    float acc[2][4][4];
    #pragma unroll
    for (int mt = 0; mt < 2; mt++)
        #pragma unroll
        for (int nt = 0; nt < 4; nt++)
            #pragma unroll
            for (int e = 0; e < 4; e++) acc[mt][nt][e] = 0.f;

    // ---- prologue: paired groups P_c = {A32(c), B(c)}, c = 0..2 ----
    #pragma unroll
    for (int c = 0; c < 3; c++) {
        uint32_t aB = sb + OFF_A32 + c * A32STG;
        uint32_t bB = sb + OFF_B + c * BSTG;
        int k0 = c * KCH;
        #pragma unroll
        for (int j = 0; j < 4; j++)
            CP_ASYNC16(aB + a32_off[j], a32_src[j] + k0);
        #pragma unroll
        for (int j = 0; j < 4; j++)
            CP_ASYNC16(bB + b_dst[j],
                       g_Wh + (size_t)brow_g[j] * Dsz + k0 + bc16[j] * 8);
        CP_COMMIT();
    }

    for (int c = 0; c < NCHK; c++) {
        int pA = c & 1;
        int rs = c % 3;       // A32 + B ring stage of chunk c
        if (c == 0)        { CP_WAIT2(); }
        else if (c == 1)   { CP_WAIT3(); }
        else if (c <= 29)  { CP_WAIT4(); }
        else if (c == 30)  { CP_WAIT2(); }
        else               { CP_WAIT0(); }

        // LDS A32(c) -> convert -> STS A16 stage pA
        {
            char* a32b = smem + OFF_A32 + rs * A32STG;
            char* a16b = smem + pA * A16STG;
            #pragma unroll
            for (int j = 0; j < 4; j++) {
                float4 v = *(const float4*)(a32b + a32_off[j]);
                uint32_t h01 = packh2(__float2half_rn(v.x), __float2half_rn(v.y));
                uint32_t h23 = packh2(__float2half_rn(v.z), __float2half_rn(v.w));
                *(uint2*)(a16b + a16_sts[j]) = make_uint2(h01, h23);
            }
        }
        __syncthreads();   // bar1: A32(c) consumed by all warps

        // issue A32(c+3) into ring stage rs (just freed)
        if (c + 3 < NCHK) {
            uint32_t aB = sb + OFF_A32 + rs * A32STG;
            int k0 = (c + 3) * KCH;
            #pragma unroll
            for (int j = 0; j < 4; j++)
                CP_ASYNC16(aB + a32_off[j], a32_src[j] + k0);
            CP_COMMIT();
        }

        // compute on A16 stage pA, B ring stage rs: 4 k16 steps
        {
            uint32_t Ahb = sb + pA * A16STG;
            uint32_t Bb  = sb + OFF_B + rs * BSTG;
            #pragma unroll
            for (int ks = 0; ks < 4; ks++) {
                uint32_t ka = (uint32_t)(ks * 32) + a_kadd;
                uint32_t kb = (uint32_t)(ks * 32) + b_kadd;
                uint32_t af[2][4];
                #pragma unroll
                for (int mt = 0; mt < 2; mt++)
                    LDSM4(af[mt][0], af[mt][1], af[mt][2], af[mt][3],
                          Ahb + a_base[mt] + (ka ^ a_xor[mt]));
                uint32_t bf[4][2];
                #pragma unroll
                for (int np = 0; np < 2; np++)
                    LDSM4(bf[2 * np][0], bf[2 * np][1], bf[2 * np + 1][0], bf[2 * np + 1][1],
                          Bb + b_base[np] + (kb ^ b_xor[np]));
                #pragma unroll
                for (int mt = 0; mt < 2; mt++)
                    #pragma unroll
                    for (int nt = 0; nt < 4; nt++)
                        mma16816h(acc[mt][nt], af[mt], bf[nt]);
            }
        }
        __syncthreads();   // bar2: B(c) consumed by all warps

        // issue B(c+3) into ring stage rs
        if (c + 3 < NCHK) {
            uint32_t bB = sb + OFF_B + rs * BSTG;
            int k0 = (c + 3) * KCH;
            #pragma unroll
            for (int j = 0; j < 4; j++)
                CP_ASYNC16(bB + b_dst[j],
                           g_Wh + (size_t)brow_g[j] * Dsz + k0 + bc16[j] * 8);
            CP_COMMIT();
        }
    }
    __syncthreads();

    // ---- epilogue-constant load (overlays A32 ring) ----
    for (int i = tid; i < Tn * Hn; i += 256)
        ((float*)(smem + SM_CONTRIB))[i] = g_contrib[i];
    for (int i = tid; i < Bsz * Hn; i += 256)
        ((float*)(smem + SM_VW3))[i] = g_vw3[i];
    if (tid < Hn) {
        ((float*)(smem + SM_B1))[tid] = b1[tid];
        ((float*)(smem + SM_WOUT))[tid] = w_out[tid];
    }
    if (tid < Bsz * Tn)
        ((float*)(smem + SM_PROBS))[tid] = g_probs[tid];
    __syncthreads();

    // ----- Epilogue: base = acc + b1 + vw3[b]; 20-topic loop, 4/sync -----
    float* s_red   = (float*)(smem + SM_RED);          // [64][4][4]
    const float* s_vw3  = (const float*)(smem + SM_VW3);
    const float* s_b1v  = (const float*)(smem + SM_B1);
    const float* s_wo   = (const float*)(smem + SM_WOUT);
    const float* s_prob = (const float*)(smem + SM_PROBS);
    const float* s_con  = (const float*)(smem + SM_CONTRIB);
    float bo = b_out_p[0];
    int r = lane >> 2, q = lane & 3;

    #pragma unroll
    for (int mt = 0; mt < 2; mt++) {
        int rg0 = m0 + wm * 32 + mt * 16 + r;
        int rg1 = rg0 + 8;
        int b0 = rg0 / ROWS_PER_B;
        int b1i = rg1 / ROWS_PER_B;
        #pragma unroll
        for (int nt = 0; nt < 4; nt++)
            #pragma unroll
            for (int e = 0; e < 2; e++) {
                int col = wn * 32 + nt * 8 + 2 * q + e;
                acc[mt][nt][e]     += s_b1v[col] + s_vw3[b0 * Hn + col];
                acc[mt][nt][2 + e] += s_b1v[col] + s_vw3[b1i * Hn + col];
            }
    }

    float wv[4][2];
    #pragma unroll
    for (int nt = 0; nt < 4; nt++)
        #pragma unroll
        for (int e = 0; e < 2; e++)
            wv[nt][e] = s_wo[wn * 32 + nt * 8 + 2 * q + e];

    float orow = 0.f;     // per-row accumulator for threads tid<64
    int myrow = m0 + (tid & 63);
    int myb = myrow / ROWS_PER_B;

    for (int tg = 0; tg < 5; tg++) {
        #pragma unroll
        for (int mt = 0; mt < 2; mt++) {
            float p0[4] = {0.f, 0.f, 0.f, 0.f};
            float p1[4] = {0.f, 0.f, 0.f, 0.f};
            #pragma unroll
            for (int tt = 0; tt < 4; tt++) {
                int t = tg * 4 + tt;
                #pragma unroll
                for (int nt = 0; nt < 4; nt++)
                    #pragma unroll
                    for (int e = 0; e < 2; e++) {
                        float cv = s_con[t * Hn + wn * 32 + nt * 8 + 2 * q + e];
                        p0[tt] = fmaf(fmaxf(acc[mt][nt][e]     + cv, 0.f), wv[nt][e], p0[tt]);
                        p1[tt] = fmaf(fmaxf(acc[mt][nt][2 + e] + cv, 0.f), wv[nt][e], p1[tt]);
                    }
            }
            #pragma unroll
            for (int tt = 0; tt < 4; tt++) {
                p0[tt] += __shfl_xor_sync(0xffffffffu, p0[tt], 1);
                p0[tt] += __shfl_xor_sync(0xffffffffu, p0[tt], 2);
                p1[tt] += __shfl_xor_sync(0xffffffffu, p1[tt], 1);
                p1[tt] += __shfl_xor_sync(0xffffffffu, p1[tt], 2);
            }
            if (q == 0) {
                int row0 = wm * 32 + mt * 16 + r;
                #pragma unroll
                for (int tt = 0; tt < 4; tt++) {
                    s_red[(row0 * 4 + wn) * 4 + tt]       = p0[tt];
                    s_red[((row0 + 8) * 4 + wn) * 4 + tt] = p1[tt];
                }
            }
        }
        __syncthreads();
        if (tid < 64) {
            #pragma unroll
            for (int tt = 0; tt < 4; tt++) {
                int t = tg * 4 + tt;
                float s = s_red[(tid * 4 + 0) * 4 + tt] + s_red[(tid * 4 + 1) * 4 + tt]
                        + s_red[(tid * 4 + 2) * 4 + tt] + s_red[(tid * 4 + 3) * 4 + tt] + bo;
                float sig = 1.f / (1.f + __expf(-s));
                float sc = sig * s_prob[myb * Tn + t] - 0.01f;
                orow += fmaxf(sc, 0.f);
            }
        }
        __syncthreads();
    }

    if (tid < 64) {
        float v = orow * (1.f / (float)Tn);
        out[myrow] = v;
        if (out_size >= 2 * Mrows) out[Mrows + myrow] = v;
    }
}

// ---------------------------------------------------------------------------
extern "C" void kernel_launch(void* const* d_in, const int* in_sizes, int n_in,
                              void* d_out, int out_size) {
    const float* batch     = (const float*)d_in[0];
    const int*   seg_len   = (const int*)  d_in[1];
    const float* concept1  = (const float*)d_in[2];
    const float* concept2  = (const float*)d_in[3];
    const float* W_enc     = (const float*)d_in[4];
    const float* b_enc     = (const float*)d_in[5];
    const float* Wc1       = (const float*)d_in[6];
    const float* Wc2       = (const float*)d_in[7];
    const float* Wt1       = (const float*)d_in[8];
    const float* bt1       = (const float*)d_in[9];
    const float* Wt2       = (const float*)d_in[10];
    const float* bt2       = (const float*)d_in[11];
    const float* topic_emb = (const float*)d_in[12];
    const float* W1        = (const float*)d_in[13];
    const float* b1        = (const float*)d_in[14];
    const float* W2        = (const float*)d_in[15];
    const float* W3        = (const float*)d_in[16];
    const float* w_out     = (const float*)d_in[17];
    const float* b_out     = (const float*)d_in[18];
    float* out = (float*)d_out;

    cudaFuncSetAttribute(gemm_tc_kernel,
                         cudaFuncAttributeMaxDynamicSharedMemorySize, SM_BYTES);

    prep_kernel<<<Tn + 64 + 32 + 1, 256>>>(W1, topic_emb, W2);
    pool_kernel<<<dim3(Dsz / 256, Ssz, Bsz * 4), 256>>>(batch, seg_len);
    encsmall_kernel<<<dim3(Bsz, 5), 1024>>>(seg_len, concept1, concept2,
                                            W_enc, Wc1, Wc2, b_enc,
                                            Wt1, bt1, Wt2, bt2, W3);
    gemm_tc_kernel<<<Mrows / 64, 256, SM_BYTES>>>(batch, b1, w_out, b_out,
                                                  out, out_size);
}